// round 10
// baseline (speedup 1.0000x reference)
#include <cuda_runtime.h>
#include <cuda_bf16.h>
#include <cstdint>
#include <math.h>

#define BB 2
#define SS 2048
#define DD 1024
#define HH 16
#define HDim 64
#define NHZ (BB*HH)

// Packed scratch: u32 = bf16_hi | bf16_lo<<16
__device__ uint32_t g_xq[4194304], g_xk[4194304], g_xv[4194304];
__device__ uint32_t g_wq[1048576], g_wk[1048576], g_wv[1048576], g_wo[1048576];
__device__ uint32_t g_qp[4194304];   // Q packed (z,s,hd), pre-scaled by 0.125
__device__ uint32_t g_kp[4194304];   // K packed (z,s,hd)
__device__ uint32_t g_vt[4194304];   // V packed transposed (z,hd,s)
__device__ uint32_t g_aop[4194304];  // attn_output packed (b,s,d)

__device__ __forceinline__ void mma_bf16(float d[4], const uint32_t a[4], const uint32_t b[2]) {
    asm volatile(
        "mma.sync.aligned.m16n8k16.row.col.f32.bf16.bf16.f32 "
        "{%0,%1,%2,%3}, {%4,%5,%6,%7}, {%8,%9}, {%0,%1,%2,%3};"
        : "+f"(d[0]), "+f"(d[1]), "+f"(d[2]), "+f"(d[3])
        : "r"(a[0]), "r"(a[1]), "r"(a[2]), "r"(a[3]), "r"(b[0]), "r"(b[1]));
}
__device__ __forceinline__ uint32_t packf(float x) {
    __nv_bfloat16 h = __float2bfloat16(x);
    __nv_bfloat16 l = __float2bfloat16(x - __bfloat162float(h));
    return (uint32_t)__bfloat16_as_ushort(h) | ((uint32_t)__bfloat16_as_ushort(l) << 16);
}
__device__ __forceinline__ void cpa16(uint32_t dst, const void* src) {
    asm volatile("cp.async.cg.shared.global [%0], [%1], 16;" :: "r"(dst), "l"(src));
}
#define CP_COMMIT() asm volatile("cp.async.commit_group;" ::: "memory")
#define CP_WAIT1() asm volatile("cp.async.wait_group 1;" ::: "memory")
#define CP_WAIT0() asm volatile("cp.async.wait_group 0;" ::: "memory")

// Fragment loads from packed smem; 1 PRMT per output register.
__device__ __forceinline__ void lda_pk(const uint32_t* S, int lda, int r, int ks, int l,
                                       uint32_t ah[4], uint32_t al[4]) {
    const uint32_t* p = S + (r + (l >> 2)) * lda + ks * 16 + 2 * (l & 3);
    uint2 q0 = *(const uint2*)p;
    uint2 q1 = *(const uint2*)(p + 8);
    uint2 q2 = *(const uint2*)(p + 8 * lda);
    uint2 q3 = *(const uint2*)(p + 8 * lda + 8);
    ah[0] = __byte_perm(q0.x, q0.y, 0x5410); al[0] = __byte_perm(q0.x, q0.y, 0x7632);
    ah[1] = __byte_perm(q2.x, q2.y, 0x5410); al[1] = __byte_perm(q2.x, q2.y, 0x7632);
    ah[2] = __byte_perm(q1.x, q1.y, 0x5410); al[2] = __byte_perm(q1.x, q1.y, 0x7632);
    ah[3] = __byte_perm(q3.x, q3.y, 0x5410); al[3] = __byte_perm(q3.x, q3.y, 0x7632);
}
__device__ __forceinline__ void ldb_pk(const uint32_t* S, int lda, int n, int ks, int l,
                                       uint32_t bh[2], uint32_t bl[2]) {
    const uint32_t* p = S + (n + (l >> 2)) * lda + ks * 16 + 2 * (l & 3);
    uint2 q0 = *(const uint2*)p;
    uint2 q1 = *(const uint2*)(p + 8);
    bh[0] = __byte_perm(q0.x, q0.y, 0x5410); bl[0] = __byte_perm(q0.x, q0.y, 0x7632);
    bh[1] = __byte_perm(q1.x, q1.y, 0x5410); bl[1] = __byte_perm(q1.x, q1.y, 0x7632);
}

// Batched packs: blockIdx.y selects the array.
__global__ void pack3_kernel(const float4* s0, const float4* s1, const float4* s2,
                             uint4* d0, uint4* d1, uint4* d2, int n4) {
    int i = blockIdx.x * 256 + threadIdx.x;
    const float4* s = (blockIdx.y == 0) ? s0 : (blockIdx.y == 1) ? s1 : s2;
    uint4* d = (blockIdx.y == 0) ? d0 : (blockIdx.y == 1) ? d1 : d2;
    if (i < n4) {
        float4 v = s[i];
        d[i] = make_uint4(packf(v.x), packf(v.y), packf(v.z), packf(v.w));
    }
}
__global__ void pack4_kernel(const float4* s0, const float4* s1, const float4* s2, const float4* s3,
                             uint4* d0, uint4* d1, uint4* d2, uint4* d3, int n4) {
    int i = blockIdx.x * 256 + threadIdx.x;
    const float4* s = (blockIdx.y == 0) ? s0 : (blockIdx.y == 1) ? s1
                    : (blockIdx.y == 2) ? s2 : s3;
    uint4* d = (blockIdx.y == 0) ? d0 : (blockIdx.y == 1) ? d1
             : (blockIdx.y == 2) ? d2 : d3;
    if (i < n4) {
        float4 v = s[i];
        d[i] = make_uint4(packf(v.x), packf(v.y), packf(v.z), packf(v.w));
    }
}

// ---------------------------------------------------------------------------
// Projection: Y = (X@W^T + bias) * scale. Tile 128x64, BK=32, 8 warps.
// blockIdx.z selects operands. mode 0: packed (z,s,hd); mode 1: packed
// transposed (z,hd,s); mode 2: fp32 row-major.
// ---------------------------------------------------------------------------
#define PJ_AW (128*40)
#define PJ_BW (64*40)
#define PJ_SM ((2*PJ_AW + 2*PJ_BW)*4)

struct PJArgs {
    const uint32_t* X[3];
    const uint32_t* W[3];
    const float*    Bs[3];
    void*           Y[3];
    int             mode[3];
    float           scl[3];
};

__global__ __launch_bounds__(256, 2) void proj_mma(PJArgs a)
{
    extern __shared__ uint32_t sm[];
    const uint32_t sb = (uint32_t)__cvta_generic_to_shared(sm);
    const int zi = blockIdx.z;
    const uint32_t* __restrict__ Xp = a.X[zi];
    const uint32_t* __restrict__ Wp = a.W[zi];
    const float* __restrict__ bias = a.Bs[zi];
    void* __restrict__ Yv = a.Y[zi];
    const int MODE = a.mode[zi];
    const float SCL = a.scl[zi];

    const int tid = threadIdx.x, w = tid >> 5, l = tid & 31;
    const int m0 = blockIdx.y << 7, n0 = blockIdx.x << 6;
    const int wm = (w & 3) << 5, wn = (w >> 2) << 5;

    auto stage = [&](int c) {
        const int bi = c & 1;
        const uint32_t aB = sb + bi * (PJ_AW * 4);
        #pragma unroll
        for (int i = 0; i < 4; i++) {
            int g = tid + (i << 8), row = g >> 3, q = g & 7;
            cpa16(aB + (uint32_t)(row * 40 + q * 4) * 4,
                  Xp + (size_t)(m0 + row) * DD + c * 32 + q * 4);
        }
        const uint32_t bB = sb + (2 * PJ_AW + bi * PJ_BW) * 4;
        #pragma unroll
        for (int i = 0; i < 2; i++) {
            int g = tid + (i << 8), row = g >> 3, q = g & 7;
            cpa16(bB + (uint32_t)(row * 40 + q * 4) * 4,
                  Wp + (size_t)(n0 + row) * DD + c * 32 + q * 4);
        }
        CP_COMMIT();
    };
    stage(0); stage(1);

    float acc[2][4][4] = {};
    for (int c = 0; c < 32; c++) {
        if (c < 31) CP_WAIT1(); else CP_WAIT0();
        __syncthreads();
        const uint32_t* As = sm + (c & 1) * PJ_AW;
        const uint32_t* Bs = sm + 2 * PJ_AW + (c & 1) * PJ_BW;
        #pragma unroll
        for (int ks = 0; ks < 2; ks++) {
            uint32_t ah[2][4], al[2][4];
            lda_pk(As, 40, wm, ks, l, ah[0], al[0]);
            lda_pk(As, 40, wm + 16, ks, l, ah[1], al[1]);
            #pragma unroll
            for (int ni = 0; ni < 4; ni++) {
                uint32_t bh[2], bl[2];
                ldb_pk(Bs, 40, wn + ni * 8, ks, l, bh, bl);
                #pragma unroll
                for (int mi = 0; mi < 2; mi++) {
                    mma_bf16(acc[mi][ni], ah[mi], bh);
                    mma_bf16(acc[mi][ni], ah[mi], bl);
                    mma_bf16(acc[mi][ni], al[mi], bh);
                }
            }
        }
        __syncthreads();
        if (c + 2 < 32) stage(c + 2);
    }

    #pragma unroll
    for (int mi = 0; mi < 2; mi++) {
        #pragma unroll
        for (int ni = 0; ni < 4; ni++) {
            const int r = m0 + wm + mi * 16 + (l >> 2);
            const int cc = n0 + wn + ni * 8 + 2 * (l & 3);
            const float b0 = __ldg(bias + cc), b1 = __ldg(bias + cc + 1);
            float y00 = (acc[mi][ni][0] + b0) * SCL, y01 = (acc[mi][ni][1] + b1) * SCL;
            float y10 = (acc[mi][ni][2] + b0) * SCL, y11 = (acc[mi][ni][3] + b1) * SCL;
            if (MODE == 2) {
                float* O = (float*)Yv;
                *(float2*)(O + (size_t)r * DD + cc) = make_float2(y00, y01);
                *(float2*)(O + (size_t)(r + 8) * DD + cc) = make_float2(y10, y11);
            } else {
                uint32_t* Y = (uint32_t*)Yv;
                const int b_ = r >> 11, s = r & (SS - 1), h = cc >> 6, hd = cc & 63;
                if (MODE == 0) {
                    size_t zb = (size_t)(b_ * HH + h) * SS;
                    *(uint2*)(Y + (zb + s) * HDim + hd) = make_uint2(packf(y00), packf(y01));
                    *(uint2*)(Y + (zb + s + 8) * HDim + hd) = make_uint2(packf(y10), packf(y11));
                } else {
                    size_t zb = (size_t)(b_ * HH + h) * HDim;
                    Y[(zb + hd) * SS + s]         = packf(y00);
                    Y[(zb + hd + 1) * SS + s]     = packf(y01);
                    Y[(zb + hd) * SS + s + 8]     = packf(y10);
                    Y[(zb + hd + 1) * SS + s + 8] = packf(y11);
                }
            }
        }
    }
}

// ---------------------------------------------------------------------------
// Scores: P = Q K^T (Q pre-scaled by 0.125). CTA = 64-row strip, loops 16
// n-tiles of 128. A resident; B double-buffered. 8 warps (2m x 4n).
// ---------------------------------------------------------------------------
#define SC_AW (64*72)
#define SC_BW (128*72)
#define SC_SM ((SC_AW + 2*SC_BW)*4)

__global__ __launch_bounds__(256) void scores_mma(
    const uint32_t* __restrict__ Qp, const uint32_t* __restrict__ Kp,
    float* __restrict__ P)
{
    extern __shared__ uint32_t sm[];
    const uint32_t sb = (uint32_t)__cvta_generic_to_shared(sm);
    const int tid = threadIdx.x, w = tid >> 5, l = tid & 31;
    const int z = blockIdx.y, m0 = blockIdx.x << 6;
    const int wm = (w & 1) << 5, wn = (w >> 1) << 5;

    auto stageB = [&](int nt) {
        const uint32_t bB = sb + (SC_AW + (nt & 1) * SC_BW) * 4;
        #pragma unroll
        for (int i = 0; i < 8; i++) {
            int g = tid + (i << 8), row = g >> 4, q = g & 15;
            cpa16(bB + (uint32_t)(row * 72 + q * 4) * 4,
                  Kp + ((size_t)z * SS + nt * 128 + row) * HDim + q * 4);
        }
    };
    #pragma unroll
    for (int i = 0; i < 4; i++) {
        int g = tid + (i << 8), row = g >> 4, q = g & 15;
        cpa16(sb + (uint32_t)(row * 72 + q * 4) * 4,
              Qp + ((size_t)z * SS + m0 + row) * HDim + q * 4);
    }
    stageB(0); CP_COMMIT();
    stageB(1); CP_COMMIT();

    float* Pz = P + (size_t)z * SS * SS;
    for (int nt = 0; nt < 16; nt++) {
        if (nt < 15) CP_WAIT1(); else CP_WAIT0();
        __syncthreads();
        const uint32_t* Bs = sm + SC_AW + (nt & 1) * SC_BW;
        float acc[2][4][4] = {};
        #pragma unroll
        for (int ks = 0; ks < 4; ks++) {
            uint32_t ah[2][4], al[2][4];
            lda_pk(sm, 72, wm, ks, l, ah[0], al[0]);
            lda_pk(sm, 72, wm + 16, ks, l, ah[1], al[1]);
            #pragma unroll
            for (int ni = 0; ni < 4; ni++) {
                uint32_t bh[2], bl[2];
                ldb_pk(Bs, 72, wn + ni * 8, ks, l, bh, bl);
                #pragma unroll
                for (int mi = 0; mi < 2; mi++) {
                    mma_bf16(acc[mi][ni], ah[mi], bh);
                    mma_bf16(acc[mi][ni], ah[mi], bl);
                    mma_bf16(acc[mi][ni], al[mi], bh);
                }
            }
        }
        __syncthreads();
        if (nt + 2 < 16) { stageB(nt + 2); CP_COMMIT(); }
        #pragma unroll
        for (int mi = 0; mi < 2; mi++) {
            #pragma unroll
            for (int ni = 0; ni < 4; ni++) {
                const int r = m0 + wm + mi * 16 + (l >> 2);
                const int cc = nt * 128 + wn + ni * 8 + 2 * (l & 3);
                *(float2*)(Pz + (size_t)r * SS + cc) =
                    make_float2(acc[mi][ni][0], acc[mi][ni][1]);
                *(float2*)(Pz + (size_t)(r + 8) * SS + cc) =
                    make_float2(acc[mi][ni][2], acc[mi][ni][3]);
            }
        }
    }
}

// ---------------------------------------------------------------------------
// AV: AO = P @ V. Tile 128x64, BK=64 (32 chunks). A converted fp32->packed
// in-kernel (register-prefetched, uint4 stores); B (V^T packed) cp.async.
// 8 warps, warp 16x64. Writes packed AO.
// ---------------------------------------------------------------------------
#define AV_AW (128*72)
#define AV_BW (64*72)
#define AV_SM ((AV_AW + 2*AV_BW)*4)

__global__ __launch_bounds__(256, 2) void av_mma(
    const float* __restrict__ P, const uint32_t* __restrict__ Vt,
    uint32_t* __restrict__ AOp)
{
    extern __shared__ uint32_t sm[];
    const uint32_t sb = (uint32_t)__cvta_generic_to_shared(sm);
    const int tid = threadIdx.x, w = tid >> 5, l = tid & 31;
    const int z = blockIdx.y, b = z >> 4, h = z & 15;
    const int m0 = blockIdx.x << 7;
    const int wm = w << 4;
    const float* Pz = P + (size_t)z * SS * SS;
    const uint32_t* Vz = Vt + (size_t)z * HDim * SS;

    auto stageB = [&](int c) {
        const uint32_t bB = sb + (AV_AW + (c & 1) * AV_BW) * 4;
        #pragma unroll
        for (int i = 0; i < 4; i++) {
            int g = tid + (i << 8), row = g >> 4, q = g & 15;
            cpa16(bB + (uint32_t)(row * 72 + q * 4) * 4,
                  Vz + (size_t)row * SS + c * 64 + q * 4);
        }
        CP_COMMIT();
    };
    stageB(0); stageB(1);

    float acc[8][4] = {};
    for (int c = 0; c < 32; c++) {
        float4 av[8];
        #pragma unroll
        for (int i = 0; i < 8; i++) {
            int g = tid + (i << 8), row = g >> 4, q = g & 15;
            av[i] = *(const float4*)(Pz + (size_t)(m0 + row) * SS + c * 64 + q * 4);
        }
        if (c < 31) CP_WAIT1(); else CP_WAIT0();
        __syncthreads();
        #pragma unroll
        for (int i = 0; i < 8; i++) {
            int g = tid + (i << 8), row = g >> 4, q = g & 15;
            *(uint4*)(sm + row * 72 + q * 4) =
                make_uint4(packf(av[i].x), packf(av[i].y), packf(av[i].z), packf(av[i].w));
        }
        __syncthreads();
        const uint32_t* Bs = sm + AV_AW + (c & 1) * AV_BW;
        #pragma unroll
        for (int ks = 0; ks < 4; ks++) {
            uint32_t ah[4], al[4];
            lda_pk(sm, 72, wm, ks, l, ah, al);
            #pragma unroll
            for (int ni = 0; ni < 8; ni++) {
                uint32_t bh[2], bl[2];
                ldb_pk(Bs, 72, ni * 8, ks, l, bh, bl);
                mma_bf16(acc[ni], ah, bh);
                mma_bf16(acc[ni], ah, bl);
                mma_bf16(acc[ni], al, bh);
            }
        }
        __syncthreads();
        if (c + 2 < 32) stageB(c + 2);
    }

    #pragma unroll
    for (int ni = 0; ni < 8; ni++) {
        const int r = m0 + wm + (l >> 2);
        const int cc = ni * 8 + 2 * (l & 3);
        uint32_t* dst = AOp + ((size_t)b * SS + r) * DD + h * HDim + cc;
        *(uint2*)dst = make_uint2(packf(acc[ni][0]), packf(acc[ni][1]));
        *(uint2*)(dst + 8 * DD) = make_uint2(packf(acc[ni][2]), packf(acc[ni][3]));
    }
}

// ---------------------------------------------------------------------------
// Row softmax in-place (fp32 P), one block per 2048-row.
// ---------------------------------------------------------------------------
__global__ __launch_bounds__(256) void softmax_kernel(float* __restrict__ P)
{
    const size_t row = blockIdx.x;
    float4* p = (float4*)(P + row * (size_t)SS);
    const int t = threadIdx.x;
    float4 a = p[t];
    float4 b = p[t + 256];
    float mx = fmaxf(fmaxf(fmaxf(a.x, a.y), fmaxf(a.z, a.w)),
                     fmaxf(fmaxf(b.x, b.y), fmaxf(b.z, b.w)));
    #pragma unroll
    for (int o = 16; o > 0; o >>= 1) mx = fmaxf(mx, __shfl_xor_sync(0xFFFFFFFFu, mx, o));
    __shared__ float rmax[8], rsum[8];
    if ((t & 31) == 0) rmax[t >> 5] = mx;
    __syncthreads();
    mx = fmaxf(fmaxf(fmaxf(rmax[0], rmax[1]), fmaxf(rmax[2], rmax[3])),
               fmaxf(fmaxf(rmax[4], rmax[5]), fmaxf(rmax[6], rmax[7])));
    a.x = __expf(a.x - mx); a.y = __expf(a.y - mx);
    a.z = __expf(a.z - mx); a.w = __expf(a.w - mx);
    b.x = __expf(b.x - mx); b.y = __expf(b.y - mx);
    b.z = __expf(b.z - mx); b.w = __expf(b.w - mx);
    float s = a.x + a.y + a.z + a.w + b.x + b.y + b.z + b.w;
    #pragma unroll
    for (int o = 16; o > 0; o >>= 1) s += __shfl_xor_sync(0xFFFFFFFFu, s, o);
    if ((t & 31) == 0) rsum[t >> 5] = s;
    __syncthreads();
    s = rsum[0] + rsum[1] + rsum[2] + rsum[3] + rsum[4] + rsum[5] + rsum[6] + rsum[7];
    const float inv = 1.0f / s;
    a.x *= inv; a.y *= inv; a.z *= inv; a.w *= inv;
    b.x *= inv; b.y *= inv; b.z *= inv; b.w *= inv;
    p[t] = a;
    p[t + 256] = b;
}

// ---------------------------------------------------------------------------
extern "C" void kernel_launch(void* const* d_in, const int* in_sizes, int n_in,
                              void* d_out, int out_size)
{
    const float* query = (const float*)d_in[0];
    const float* key_  = (const float*)d_in[1];
    const float* value = (const float*)d_in[2];
    const float* wq = (const float*)d_in[3];
    const float* bq = (const float*)d_in[4];
    const float* wk = (const float*)d_in[5];
    const float* bk = (const float*)d_in[6];
    const float* wv = (const float*)d_in[7];
    const float* bv = (const float*)d_in[8];
    const float* wo = (const float*)d_in[9];
    const float* bo = (const float*)d_in[10];

    float* out = (float*)d_out;                 // (B,S,D)
    float* attnw = out + (size_t)BB * SS * DD;  // (B,H,S,S)

    uint32_t *xq, *xk, *xv, *pwq, *pwk, *pwv, *pwo, *qp, *kp, *vt, *aop;
    cudaGetSymbolAddress((void**)&xq, g_xq);
    cudaGetSymbolAddress((void**)&xk, g_xk);
    cudaGetSymbolAddress((void**)&xv, g_xv);
    cudaGetSymbolAddress((void**)&pwq, g_wq);
    cudaGetSymbolAddress((void**)&pwk, g_wk);
    cudaGetSymbolAddress((void**)&pwv, g_wv);
    cudaGetSymbolAddress((void**)&pwo, g_wo);
    cudaGetSymbolAddress((void**)&qp, g_qp);
    cudaGetSymbolAddress((void**)&kp, g_kp);
    cudaGetSymbolAddress((void**)&vt, g_vt);
    cudaGetSymbolAddress((void**)&aop, g_aop);

    cudaFuncSetAttribute(proj_mma,   cudaFuncAttributeMaxDynamicSharedMemorySize, PJ_SM);
    cudaFuncSetAttribute(scores_mma, cudaFuncAttributeMaxDynamicSharedMemorySize, SC_SM);
    cudaFuncSetAttribute(av_mma,     cudaFuncAttributeMaxDynamicSharedMemorySize, AV_SM);

    const int nin4 = (BB * SS * DD) / 4;   // 1048576
    const int nw4  = (DD * DD) / 4;        // 262144
    pack3_kernel<<<dim3(nin4 / 256, 3), 256>>>(
        (const float4*)query, (const float4*)key_, (const float4*)value,
        (uint4*)xq, (uint4*)xk, (uint4*)xv, nin4);
    pack4_kernel<<<dim3(nw4 / 256, 4), 256>>>(
        (const float4*)wq, (const float4*)wk, (const float4*)wv, (const float4*)wo,
        (uint4*)pwq, (uint4*)pwk, (uint4*)pwv, (uint4*)pwo, nw4);

    // Merged Q/K/V projection: one launch, blockIdx.z selects operands.
    // Q is pre-scaled by 1/sqrt(HD)=0.125 (exact power of 2).
    PJArgs qkv;
    qkv.X[0] = xq;  qkv.W[0] = pwq; qkv.Bs[0] = bq; qkv.Y[0] = qp;  qkv.mode[0] = 0; qkv.scl[0] = 0.125f;
    qkv.X[1] = xk;  qkv.W[1] = pwk; qkv.Bs[1] = bk; qkv.Y[1] = kp;  qkv.mode[1] = 0; qkv.scl[1] = 1.0f;
    qkv.X[2] = xv;  qkv.W[2] = pwv; qkv.Bs[2] = bv; qkv.Y[2] = vt;  qkv.mode[2] = 1; qkv.scl[2] = 1.0f;
    proj_mma<<<dim3(DD / 64, (BB * SS) / 128, 3), 256, PJ_SM>>>(qkv);

    scores_mma<<<dim3(SS / 64, NHZ), 256, SC_SM>>>(qp, kp, attnw);

    softmax_kernel<<<NHZ * SS, 256>>>(attnw);

    av_mma<<<dim3(SS / 128, NHZ), 256, AV_SM>>>(attnw, vt, aop);

    // Final O projection (mode 2), same kernel, grid.z = 1.
    PJArgs oargs;
    oargs.X[0] = aop; oargs.W[0] = pwo; oargs.Bs[0] = bo; oargs.Y[0] = out; oargs.mode[0] = 2; oargs.scl[0] = 1.0f;
    oargs.X[1] = aop; oargs.W[1] = pwo; oargs.Bs[1] = bo; oargs.Y[1] = out; oargs.mode[1] = 2; oargs.scl[1] = 1.0f;
    oargs.X[2] = aop; oargs.W[2] = pwo; oargs.Bs[2] = bo; oargs.Y[2] = out; oargs.mode[2] = 2; oargs.scl[2] = 1.0f;
    proj_mma<<<dim3(DD / 64, (BB * SS) / 128, 1), 256, PJ_SM>>>(oargs);
}

// round 13
// speedup vs baseline: 1.4550x; 1.4550x over previous
#include <cuda_runtime.h>
#include <cuda_bf16.h>
#include <cstdint>
#include <math.h>

#define BB 2
#define SS 2048
#define DD 1024
#define HH 16
#define HDim 64
#define NHZ (BB*HH)

// Packed scratch: u32 = bf16_hi | bf16_lo<<16
__device__ uint32_t g_xq[4194304], g_xk[4194304], g_xv[4194304];
__device__ uint32_t g_wq[1048576], g_wk[1048576], g_wv[1048576], g_wo[1048576];
__device__ uint32_t g_qp[4194304];   // Q packed (z,s,hd), pre-scaled by 0.125
__device__ uint32_t g_kp[4194304];   // K packed (z,s,hd)
__device__ uint32_t g_vt[4194304];   // V packed transposed (z,hd,s)
__device__ uint32_t g_aop[4194304];  // attn_output packed (b,s,d)

__device__ __forceinline__ void mma_bf16(float d[4], const uint32_t a[4], const uint32_t b[2]) {
    asm volatile(
        "mma.sync.aligned.m16n8k16.row.col.f32.bf16.bf16.f32 "
        "{%0,%1,%2,%3}, {%4,%5,%6,%7}, {%8,%9}, {%0,%1,%2,%3};"
        : "+f"(d[0]), "+f"(d[1]), "+f"(d[2]), "+f"(d[3])
        : "r"(a[0]), "r"(a[1]), "r"(a[2]), "r"(a[3]), "r"(b[0]), "r"(b[1]));
}
__device__ __forceinline__ uint32_t packf(float x) {
    __nv_bfloat16 h = __float2bfloat16(x);
    __nv_bfloat16 l = __float2bfloat16(x - __bfloat162float(h));
    return (uint32_t)__bfloat16_as_ushort(h) | ((uint32_t)__bfloat16_as_ushort(l) << 16);
}
__device__ __forceinline__ void cpa16(uint32_t dst, const void* src) {
    asm volatile("cp.async.cg.shared.global [%0], [%1], 16;" :: "r"(dst), "l"(src));
}
#define CP_COMMIT() asm volatile("cp.async.commit_group;" ::: "memory")
#define CP_WAIT1() asm volatile("cp.async.wait_group 1;" ::: "memory")
#define CP_WAIT0() asm volatile("cp.async.wait_group 0;" ::: "memory")

// Fragment loads from packed smem; 1 PRMT per output register.
__device__ __forceinline__ void lda_pk(const uint32_t* S, int lda, int r, int ks, int l,
                                       uint32_t ah[4], uint32_t al[4]) {
    const uint32_t* p = S + (r + (l >> 2)) * lda + ks * 16 + 2 * (l & 3);
    uint2 q0 = *(const uint2*)p;
    uint2 q1 = *(const uint2*)(p + 8);
    uint2 q2 = *(const uint2*)(p + 8 * lda);
    uint2 q3 = *(const uint2*)(p + 8 * lda + 8);
    ah[0] = __byte_perm(q0.x, q0.y, 0x5410); al[0] = __byte_perm(q0.x, q0.y, 0x7632);
    ah[1] = __byte_perm(q2.x, q2.y, 0x5410); al[1] = __byte_perm(q2.x, q2.y, 0x7632);
    ah[2] = __byte_perm(q1.x, q1.y, 0x5410); al[2] = __byte_perm(q1.x, q1.y, 0x7632);
    ah[3] = __byte_perm(q3.x, q3.y, 0x5410); al[3] = __byte_perm(q3.x, q3.y, 0x7632);
}
__device__ __forceinline__ void ldb_pk(const uint32_t* S, int lda, int n, int ks, int l,
                                       uint32_t bh[2], uint32_t bl[2]) {
    const uint32_t* p = S + (n + (l >> 2)) * lda + ks * 16 + 2 * (l & 3);
    uint2 q0 = *(const uint2*)p;
    uint2 q1 = *(const uint2*)(p + 8);
    bh[0] = __byte_perm(q0.x, q0.y, 0x5410); bl[0] = __byte_perm(q0.x, q0.y, 0x7632);
    bh[1] = __byte_perm(q1.x, q1.y, 0x5410); bl[1] = __byte_perm(q1.x, q1.y, 0x7632);
}

// Batched packs: blockIdx.y selects the array.
__global__ void pack3_kernel(const float4* s0, const float4* s1, const float4* s2,
                             uint4* d0, uint4* d1, uint4* d2, int n4) {
    int i = blockIdx.x * 256 + threadIdx.x;
    const float4* s = (blockIdx.y == 0) ? s0 : (blockIdx.y == 1) ? s1 : s2;
    uint4* d = (blockIdx.y == 0) ? d0 : (blockIdx.y == 1) ? d1 : d2;
    if (i < n4) {
        float4 v = s[i];
        d[i] = make_uint4(packf(v.x), packf(v.y), packf(v.z), packf(v.w));
    }
}
__global__ void pack4_kernel(const float4* s0, const float4* s1, const float4* s2, const float4* s3,
                             uint4* d0, uint4* d1, uint4* d2, uint4* d3, int n4) {
    int i = blockIdx.x * 256 + threadIdx.x;
    const float4* s = (blockIdx.y == 0) ? s0 : (blockIdx.y == 1) ? s1
                    : (blockIdx.y == 2) ? s2 : s3;
    uint4* d = (blockIdx.y == 0) ? d0 : (blockIdx.y == 1) ? d1
             : (blockIdx.y == 2) ? d2 : d3;
    if (i < n4) {
        float4 v = s[i];
        d[i] = make_uint4(packf(v.x), packf(v.y), packf(v.z), packf(v.w));
    }
}

// ---------------------------------------------------------------------------
// Projection: Y = (X@W^T + bias) * scale. Tile 128x64, BK=32, 8 warps.
// blockIdx.z selects operands. mode 0: packed (z,s,hd); mode 1: packed
// transposed (z,hd,s); mode 2: fp32 row-major.
// ---------------------------------------------------------------------------
#define PJ_AW (128*40)
#define PJ_BW (64*40)
#define PJ_SM ((2*PJ_AW + 2*PJ_BW)*4)

struct PJArgs {
    const uint32_t* X[3];
    const uint32_t* W[3];
    const float*    Bs[3];
    void*           Y[3];
    int             mode[3];
    float           scl[3];
};

__global__ __launch_bounds__(256, 2) void proj_mma(PJArgs a)
{
    extern __shared__ uint32_t sm[];
    const uint32_t sb = (uint32_t)__cvta_generic_to_shared(sm);
    const int zi = blockIdx.z;
    const uint32_t* __restrict__ Xp = a.X[zi];
    const uint32_t* __restrict__ Wp = a.W[zi];
    const float* __restrict__ bias = a.Bs[zi];
    void* __restrict__ Yv = a.Y[zi];
    const int MODE = a.mode[zi];
    const float SCL = a.scl[zi];

    const int tid = threadIdx.x, w = tid >> 5, l = tid & 31;
    const int m0 = blockIdx.y << 7, n0 = blockIdx.x << 6;
    const int wm = (w & 3) << 5, wn = (w >> 2) << 5;

    auto stage = [&](int c) {
        const int bi = c & 1;
        const uint32_t aB = sb + bi * (PJ_AW * 4);
        #pragma unroll
        for (int i = 0; i < 4; i++) {
            int g = tid + (i << 8), row = g >> 3, q = g & 7;
            cpa16(aB + (uint32_t)(row * 40 + q * 4) * 4,
                  Xp + (size_t)(m0 + row) * DD + c * 32 + q * 4);
        }
        const uint32_t bB = sb + (2 * PJ_AW + bi * PJ_BW) * 4;
        #pragma unroll
        for (int i = 0; i < 2; i++) {
            int g = tid + (i << 8), row = g >> 3, q = g & 7;
            cpa16(bB + (uint32_t)(row * 40 + q * 4) * 4,
                  Wp + (size_t)(n0 + row) * DD + c * 32 + q * 4);
        }
        CP_COMMIT();
    };
    stage(0); stage(1);

    float acc[2][4][4] = {};
    for (int c = 0; c < 32; c++) {
        if (c < 31) CP_WAIT1(); else CP_WAIT0();
        __syncthreads();
        const uint32_t* As = sm + (c & 1) * PJ_AW;
        const uint32_t* Bs = sm + 2 * PJ_AW + (c & 1) * PJ_BW;
        #pragma unroll
        for (int ks = 0; ks < 2; ks++) {
            uint32_t ah[2][4], al[2][4];
            lda_pk(As, 40, wm, ks, l, ah[0], al[0]);
            lda_pk(As, 40, wm + 16, ks, l, ah[1], al[1]);
            #pragma unroll
            for (int ni = 0; ni < 4; ni++) {
                uint32_t bh[2], bl[2];
                ldb_pk(Bs, 40, wn + ni * 8, ks, l, bh, bl);
                #pragma unroll
                for (int mi = 0; mi < 2; mi++) {
                    mma_bf16(acc[mi][ni], ah[mi], bh);
                    mma_bf16(acc[mi][ni], ah[mi], bl);
                    mma_bf16(acc[mi][ni], al[mi], bh);
                }
            }
        }
        __syncthreads();
        if (c + 2 < 32) stage(c + 2);
    }

    #pragma unroll
    for (int mi = 0; mi < 2; mi++) {
        #pragma unroll
        for (int ni = 0; ni < 4; ni++) {
            const int r = m0 + wm + mi * 16 + (l >> 2);
            const int cc = n0 + wn + ni * 8 + 2 * (l & 3);
            const float b0 = __ldg(bias + cc), b1 = __ldg(bias + cc + 1);
            float y00 = (acc[mi][ni][0] + b0) * SCL, y01 = (acc[mi][ni][1] + b1) * SCL;
            float y10 = (acc[mi][ni][2] + b0) * SCL, y11 = (acc[mi][ni][3] + b1) * SCL;
            if (MODE == 2) {
                float* O = (float*)Yv;
                *(float2*)(O + (size_t)r * DD + cc) = make_float2(y00, y01);
                *(float2*)(O + (size_t)(r + 8) * DD + cc) = make_float2(y10, y11);
            } else {
                uint32_t* Y = (uint32_t*)Yv;
                const int b_ = r >> 11, s = r & (SS - 1), h = cc >> 6, hd = cc & 63;
                if (MODE == 0) {
                    size_t zb = (size_t)(b_ * HH + h) * SS;
                    *(uint2*)(Y + (zb + s) * HDim + hd) = make_uint2(packf(y00), packf(y01));
                    *(uint2*)(Y + (zb + s + 8) * HDim + hd) = make_uint2(packf(y10), packf(y11));
                } else {
                    size_t zb = (size_t)(b_ * HH + h) * HDim;
                    Y[(zb + hd) * SS + s]         = packf(y00);
                    Y[(zb + hd + 1) * SS + s]     = packf(y01);
                    Y[(zb + hd) * SS + s + 8]     = packf(y10);
                    Y[(zb + hd + 1) * SS + s + 8] = packf(y11);
                }
            }
        }
    }
}

// ---------------------------------------------------------------------------
// Scores: P = Q K^T (Q pre-scaled by 0.125). CTA = 64-row strip, loops 16
// n-tiles of 128. A resident; B double-buffered. 8 warps (2m x 4n).
// ---------------------------------------------------------------------------
#define SC_AW (64*72)
#define SC_BW (128*72)
#define SC_SM ((SC_AW + 2*SC_BW)*4)

__global__ __launch_bounds__(256) void scores_mma(
    const uint32_t* __restrict__ Qp, const uint32_t* __restrict__ Kp,
    float* __restrict__ P)
{
    extern __shared__ uint32_t sm[];
    const uint32_t sb = (uint32_t)__cvta_generic_to_shared(sm);
    const int tid = threadIdx.x, w = tid >> 5, l = tid & 31;
    const int z = blockIdx.y, m0 = blockIdx.x << 6;
    const int wm = (w & 1) << 5, wn = (w >> 1) << 5;

    auto stageB = [&](int nt) {
        const uint32_t bB = sb + (SC_AW + (nt & 1) * SC_BW) * 4;
        #pragma unroll
        for (int i = 0; i < 8; i++) {
            int g = tid + (i << 8), row = g >> 4, q = g & 15;
            cpa16(bB + (uint32_t)(row * 72 + q * 4) * 4,
                  Kp + ((size_t)z * SS + nt * 128 + row) * HDim + q * 4);
        }
    };
    #pragma unroll
    for (int i = 0; i < 4; i++) {
        int g = tid + (i << 8), row = g >> 4, q = g & 15;
        cpa16(sb + (uint32_t)(row * 72 + q * 4) * 4,
              Qp + ((size_t)z * SS + m0 + row) * HDim + q * 4);
    }
    stageB(0); CP_COMMIT();
    stageB(1); CP_COMMIT();

    float* Pz = P + (size_t)z * SS * SS;
    for (int nt = 0; nt < 16; nt++) {
        if (nt < 15) CP_WAIT1(); else CP_WAIT0();
        __syncthreads();
        const uint32_t* Bs = sm + SC_AW + (nt & 1) * SC_BW;
        float acc[2][4][4] = {};
        #pragma unroll
        for (int ks = 0; ks < 4; ks++) {
            uint32_t ah[2][4], al[2][4];
            lda_pk(sm, 72, wm, ks, l, ah[0], al[0]);
            lda_pk(sm, 72, wm + 16, ks, l, ah[1], al[1]);
            #pragma unroll
            for (int ni = 0; ni < 4; ni++) {
                uint32_t bh[2], bl[2];
                ldb_pk(Bs, 72, wn + ni * 8, ks, l, bh, bl);
                #pragma unroll
                for (int mi = 0; mi < 2; mi++) {
                    mma_bf16(acc[mi][ni], ah[mi], bh);
                    mma_bf16(acc[mi][ni], ah[mi], bl);
                    mma_bf16(acc[mi][ni], al[mi], bh);
                }
            }
        }
        __syncthreads();
        if (nt + 2 < 16) { stageB(nt + 2); CP_COMMIT(); }
        #pragma unroll
        for (int mi = 0; mi < 2; mi++) {
            #pragma unroll
            for (int ni = 0; ni < 4; ni++) {
                const int r = m0 + wm + mi * 16 + (l >> 2);
                const int cc = nt * 128 + wn + ni * 8 + 2 * (l & 3);
                *(float2*)(Pz + (size_t)r * SS + cc) =
                    make_float2(acc[mi][ni][0], acc[mi][ni][1]);
                *(float2*)(Pz + (size_t)(r + 8) * SS + cc) =
                    make_float2(acc[mi][ni][2], acc[mi][ni][3]);
            }
        }
    }
}

// ---------------------------------------------------------------------------
// AV: AO = P @ V. Tile 128x64, BK=64 (32 chunks). A converted fp32->packed
// in-kernel (register-prefetched, uint4 stores); B (V^T packed) cp.async.
// 8 warps, warp 16x64. Writes packed AO.
// ---------------------------------------------------------------------------
#define AV_AW (128*72)
#define AV_BW (64*72)
#define AV_SM ((AV_AW + 2*AV_BW)*4)

__global__ __launch_bounds__(256, 2) void av_mma(
    const float* __restrict__ P, const uint32_t* __restrict__ Vt,
    uint32_t* __restrict__ AOp)
{
    extern __shared__ uint32_t sm[];
    const uint32_t sb = (uint32_t)__cvta_generic_to_shared(sm);
    const int tid = threadIdx.x, w = tid >> 5, l = tid & 31;
    const int z = blockIdx.y, b = z >> 4, h = z & 15;
    const int m0 = blockIdx.x << 7;
    const int wm = w << 4;
    const float* Pz = P + (size_t)z * SS * SS;
    const uint32_t* Vz = Vt + (size_t)z * HDim * SS;

    auto stageB = [&](int c) {
        const uint32_t bB = sb + (AV_AW + (c & 1) * AV_BW) * 4;
        #pragma unroll
        for (int i = 0; i < 4; i++) {
            int g = tid + (i << 8), row = g >> 4, q = g & 15;
            cpa16(bB + (uint32_t)(row * 72 + q * 4) * 4,
                  Vz + (size_t)row * SS + c * 64 + q * 4);
        }
        CP_COMMIT();
    };
    stageB(0); stageB(1);

    float acc[8][4] = {};
    for (int c = 0; c < 32; c++) {
        float4 av[8];
        #pragma unroll
        for (int i = 0; i < 8; i++) {
            int g = tid + (i << 8), row = g >> 4, q = g & 15;
            av[i] = *(const float4*)(Pz + (size_t)(m0 + row) * SS + c * 64 + q * 4);
        }
        if (c < 31) CP_WAIT1(); else CP_WAIT0();
        __syncthreads();
        #pragma unroll
        for (int i = 0; i < 8; i++) {
            int g = tid + (i << 8), row = g >> 4, q = g & 15;
            *(uint4*)(sm + row * 72 + q * 4) =
                make_uint4(packf(av[i].x), packf(av[i].y), packf(av[i].z), packf(av[i].w));
        }
        __syncthreads();
        const uint32_t* Bs = sm + AV_AW + (c & 1) * AV_BW;
        #pragma unroll
        for (int ks = 0; ks < 4; ks++) {
            uint32_t ah[4], al[4];
            lda_pk(sm, 72, wm, ks, l, ah, al);
            #pragma unroll
            for (int ni = 0; ni < 8; ni++) {
                uint32_t bh[2], bl[2];
                ldb_pk(Bs, 72, ni * 8, ks, l, bh, bl);
                mma_bf16(acc[ni], ah, bh);
                mma_bf16(acc[ni], ah, bl);
                mma_bf16(acc[ni], al, bh);
            }
        }
        __syncthreads();
        if (c + 2 < 32) stageB(c + 2);
    }

    #pragma unroll
    for (int ni = 0; ni < 8; ni++) {
        const int r = m0 + wm + (l >> 2);
        const int cc = ni * 8 + 2 * (l & 3);
        uint32_t* dst = AOp + ((size_t)b * SS + r) * DD + h * HDim + cc;
        *(uint2*)dst = make_uint2(packf(acc[ni][0]), packf(acc[ni][1]));
        *(uint2*)(dst + 8 * DD) = make_uint2(packf(acc[ni][2]), packf(acc[ni][3]));
    }
}

// ---------------------------------------------------------------------------
// Row softmax in-place (fp32 P), one block per 2048-row.
// ---------------------------------------------------------------------------
__global__ __launch_bounds__(256) void softmax_kernel(float* __restrict__ P)
{
    const size_t row = blockIdx.x;
    float4* p = (float4*)(P + row * (size_t)SS);
    const int t = threadIdx.x;
    float4 a = p[t];
    float4 b = p[t + 256];
    float mx = fmaxf(fmaxf(fmaxf(a.x, a.y), fmaxf(a.z, a.w)),
                     fmaxf(fmaxf(b.x, b.y), fmaxf(b.z, b.w)));
    #pragma unroll
    for (int o = 16; o > 0; o >>= 1) mx = fmaxf(mx, __shfl_xor_sync(0xFFFFFFFFu, mx, o));
    __shared__ float rmax[8], rsum[8];
    if ((t & 31) == 0) rmax[t >> 5] = mx;
    __syncthreads();
    mx = fmaxf(fmaxf(fmaxf(rmax[0], rmax[1]), fmaxf(rmax[2], rmax[3])),
               fmaxf(fmaxf(rmax[4], rmax[5]), fmaxf(rmax[6], rmax[7])));
    a.x = __expf(a.x - mx); a.y = __expf(a.y - mx);
    a.z = __expf(a.z - mx); a.w = __expf(a.w - mx);
    b.x = __expf(b.x - mx); b.y = __expf(b.y - mx);
    b.z = __expf(b.z - mx); b.w = __expf(b.w - mx);
    float s = a.x + a.y + a.z + a.w + b.x + b.y + b.z + b.w;
    #pragma unroll
    for (int o = 16; o > 0; o >>= 1) s += __shfl_xor_sync(0xFFFFFFFFu, s, o);
    if ((t & 31) == 0) rsum[t >> 5] = s;
    __syncthreads();
    s = rsum[0] + rsum[1] + rsum[2] + rsum[3] + rsum[4] + rsum[5] + rsum[6] + rsum[7];
    const float inv = 1.0f / s;
    a.x *= inv; a.y *= inv; a.z *= inv; a.w *= inv;
    b.x *= inv; b.y *= inv; b.z *= inv; b.w *= inv;
    p[t] = a;
    p[t + 256] = b;
}

// ---------------------------------------------------------------------------
extern "C" void kernel_launch(void* const* d_in, const int* in_sizes, int n_in,
                              void* d_out, int out_size)
{
    const float* query = (const float*)d_in[0];
    const float* key_  = (const float*)d_in[1];
    const float* value = (const float*)d_in[2];
    const float* wq = (const float*)d_in[3];
    const float* bq = (const float*)d_in[4];
    const float* wk = (const float*)d_in[5];
    const float* bk = (const float*)d_in[6];
    const float* wv = (const float*)d_in[7];
    const float* bv = (const float*)d_in[8];
    const float* wo = (const float*)d_in[9];
    const float* bo = (const float*)d_in[10];

    float* out = (float*)d_out;                 // (B,S,D)
    float* attnw = out + (size_t)BB * SS * DD;  // (B,H,S,S)

    uint32_t *xq, *xk, *xv, *pwq, *pwk, *pwv, *pwo, *qp, *kp, *vt, *aop;
    cudaGetSymbolAddress((void**)&xq, g_xq);
    cudaGetSymbolAddress((void**)&xk, g_xk);
    cudaGetSymbolAddress((void**)&xv, g_xv);
    cudaGetSymbolAddress((void**)&pwq, g_wq);
    cudaGetSymbolAddress((void**)&pwk, g_wk);
    cudaGetSymbolAddress((void**)&pwv, g_wv);
    cudaGetSymbolAddress((void**)&pwo, g_wo);
    cudaGetSymbolAddress((void**)&qp, g_qp);
    cudaGetSymbolAddress((void**)&kp, g_kp);
    cudaGetSymbolAddress((void**)&vt, g_vt);
    cudaGetSymbolAddress((void**)&aop, g_aop);

    cudaFuncSetAttribute(proj_mma,   cudaFuncAttributeMaxDynamicSharedMemorySize, PJ_SM);
    cudaFuncSetAttribute(scores_mma, cudaFuncAttributeMaxDynamicSharedMemorySize, SC_SM);
    cudaFuncSetAttribute(av_mma,     cudaFuncAttributeMaxDynamicSharedMemorySize, AV_SM);

    const int nin4 = (BB * SS * DD) / 4;   // 1048576
    const int nw4  = (DD * DD) / 4;        // 262144
    pack3_kernel<<<dim3(nin4 / 256, 3), 256>>>(
        (const float4*)query, (const float4*)key_, (const float4*)value,
        (uint4*)xq, (uint4*)xk, (uint4*)xv, nin4);
    pack4_kernel<<<dim3(nw4 / 256, 4), 256>>>(
        (const float4*)wq, (const float4*)wk, (const float4*)wv, (const float4*)wo,
        (uint4*)pwq, (uint4*)pwk, (uint4*)pwv, (uint4*)pwo, nw4);

    // Merged Q/K/V projection: one launch, blockIdx.z selects operands.
    // Q is pre-scaled by 1/sqrt(HD)=0.125 (exact power of 2).
    PJArgs qkv;
    qkv.X[0] = xq;  qkv.W[0] = pwq; qkv.Bs[0] = bq; qkv.Y[0] = qp;  qkv.mode[0] = 0; qkv.scl[0] = 0.125f;
    qkv.X[1] = xk;  qkv.W[1] = pwk; qkv.Bs[1] = bk; qkv.Y[1] = kp;  qkv.mode[1] = 0; qkv.scl[1] = 1.0f;
    qkv.X[2] = xv;  qkv.W[2] = pwv; qkv.Bs[2] = bv; qkv.Y[2] = vt;  qkv.mode[2] = 1; qkv.scl[2] = 1.0f;
    proj_mma<<<dim3(DD / 64, (BB * SS) / 128, 3), 256, PJ_SM>>>(qkv);

    scores_mma<<<dim3(SS / 64, NHZ), 256, SC_SM>>>(qp, kp, attnw);

    softmax_kernel<<<NHZ * SS, 256>>>(attnw);

    av_mma<<<dim3(SS / 128, NHZ), 256, AV_SM>>>(attnw, vt, aop);

    // Final O projection (mode 2), same kernel, grid.z = 1.
    PJArgs oargs;
    oargs.X[0] = aop; oargs.W[0] = pwo; oargs.Bs[0] = bo; oargs.Y[0] = out; oargs.mode[0] = 2; oargs.scl[0] = 1.0f;
    oargs.X[1] = aop; oargs.W[1] = pwo; oargs.Bs[1] = bo; oargs.Y[1] = out; oargs.mode[1] = 2; oargs.scl[1] = 1.0f;
    oargs.X[2] = aop; oargs.W[2] = pwo; oargs.Bs[2] = bo; oargs.Y[2] = out; oargs.mode[2] = 2; oargs.scl[2] = 1.0f;
    proj_mma<<<dim3(DD / 64, (BB * SS) / 128, 1), 256, PJ_SM>>>(oargs);
}